// round 5
// baseline (speedup 1.0000x reference)
#include <cuda_runtime.h>
#include <cuda_bf16.h>
#include <math.h>

// S4D kernel init:  out[h,l] = 2 * Re( sum_n Ccf[h,n] * exp(dtA[h,n] * l) )
// l = j*128 + i ;  out[h,j,i] = sum_n Px[n,j]*Qr[n,i] - Py[n,j]*Qi[n,i]
//
// Round-5: P operands fused into one float4 (px0,px1,-py0,-py1) per (n,jpair)
// read as a single LDS.128 broadcast and consumed as two u64 halves with zero
// repacking. Crossbar traffic drops 16->12 wf per warp per n, making the
// FFMA2 pipe the sole bottleneck (2048 vs 1536 cyc per SMSP per block).

#define N2 32
#define NP 16          // n-rows per Q pass
#define TT 128
#define TTP 129        // padded sQ row (float2 units)
#define NTHREADS 128
#define NJ 32
#define NJP 16         // global j-pairs

typedef unsigned long long u64;

__device__ __forceinline__ u64 pack2(float x, float y) {
    u64 r; asm("mov.b64 %0, {%1, %2};" : "=l"(r) : "f"(x), "f"(y)); return r;
}
__device__ __forceinline__ u64 fma2(u64 a, u64 b, u64 c) {
    u64 d; asm("fma.rn.f32x2 %0, %1, %2, %3;" : "=l"(d) : "l"(a), "l"(b), "l"(c)); return d;
}
__device__ __forceinline__ float2 unpack2(u64 v) {
    float2 f; asm("mov.b64 {%0, %1}, %2;" : "=f"(f.x), "=f"(f.y) : "l"(v)); return f;
}

__global__ __launch_bounds__(NTHREADS, 7)
void s4d_vandermonde_kernel(
    const float* __restrict__ log_dt,
    const float* __restrict__ C,          // (H, N2, 2)
    const float* __restrict__ log_A_real, // (H, N2)
    const float* __restrict__ A_imag,     // (H, N2)
    float* __restrict__ out,              // (H, L)
    int L)
{
    __shared__ float2 sQ[NP][TTP];      // 16.1 KB, padded, reused across passes
    __shared__ float4 sPc[N2][NJP];     //  8 KB : (px0, px1, -py0, -py1)
    __shared__ float2 sW[N2];           // exp(dtA)
    __shared__ float  sAr[N2], sAi[N2];
    __shared__ float2 sCcf[N2];

    const int h    = blockIdx.x;
    const int tid  = threadIdx.x;
    const int lane = tid & 31;
    const int jt   = tid >> 5;          // warp id = j-tile (8 j each)

    // ---------- Phase 0: per-(h,n) coefficients ----------
    if (tid < N2) {
        const int n = tid;
        const int g = h * N2 + n;
        float dt  = expf(log_dt[h]);
        float ar0 = -expf(log_A_real[g]);   // Re(A)
        float ai0 = A_imag[g];              // Im(A)
        float ar  = ar0 * dt;               // Re(dtA)
        float ai  = ai0 * dt;               // Im(dtA)
        float er  = expf(ar), s, c;
        sincosf(ai, &s, &c);
        float wr = er * c, wi = er * s;     // w = exp(dtA)
        sW[n]  = make_float2(wr, wi);
        sAr[n] = ar;
        sAi[n] = ai;
        // D = (exp(dtA) - 1) / A
        float Er = wr - 1.0f, Ei = wi;
        float inv = 1.0f / (ar0 * ar0 + ai0 * ai0);
        float Dr = (Er * ar0 + Ei * ai0) * inv;
        float Di = (Ei * ar0 - Er * ai0) * inv;
        // Ccf = 2 * Cc * D
        float cr = C[2 * g], ci = C[2 * g + 1];
        sCcf[n] = make_float2(2.0f * (cr * Dr - ci * Di),
                              2.0f * (cr * Di + ci * Dr));
    }
    __syncthreads();

    // ---------- Phase 2: fused P: sPc[n][jp] = (px0, px1, -py0, -py1) ----------
    #pragma unroll
    for (int r = 0; r < (N2 * NJP) / NTHREADS; r++) {   // 4 iters
        int idx = r * NTHREADS + tid;
        int n   = idx >> 4;         // 0..31
        int jp  = idx & 15;         // global j-pair
        float ar = sAr[n], ai = sAi[n];
        float x0 = (float)(TT * (2 * jp));
        float x1 = (float)(TT * (2 * jp + 1));
        float e0 = expf(ar * x0), s0, c0;
        sincosf(ai * x0, &s0, &c0);
        float e1 = expf(ar * x1), s1, c1;
        sincosf(ai * x1, &s1, &c1);
        sPc[n][jp] = make_float4(e0 * c0, e1 * c1, -e0 * s0, -e1 * s1);
    }

    // ---------- Accumulators: acc[i][jp], lo = j=8*jt+2*jp, hi = +1 ----------
    u64 acc[4][4];
    #pragma unroll
    for (int a = 0; a < 4; a++)
        #pragma unroll
        for (int b = 0; b < 4; b++) acc[a][b] = 0ULL;

    #pragma unroll
    for (int pass = 0; pass < 2; pass++) {
        // ----- Q build: nl lane-fast so STS lanes spread across banks -----
        {
            const int nl  = tid & 15;           // 0..15 local row (lane-fast)
            const int n   = pass * NP + nl;     // global n
            const int seg = tid >> 4;           // 0..7 -> i = 16*seg..
            float ar = sAr[n], ai = sAi[n];
            float x  = 16.0f * (float)seg;
            float e  = expf(ar * x), s, c;
            sincosf(ai * x, &s, &c);
            float zr0 = e * c, zi0 = e * s;     // exp(dtA * 16*seg)
            float2 cc = sCcf[n];
            float zr = cc.x * zr0 - cc.y * zi0; // Ccf * anchor
            float zi = cc.x * zi0 + cc.y * zr0;
            float2 w = sW[n];
            const int ibase = seg * 16;
            #pragma unroll
            for (int k = 0; k < 16; k++) {
                sQ[nl][ibase + k] = make_float2(zr, zi);
                float nzr = zr * w.x - zi * w.y;
                float nzi = zr * w.y + zi * w.x;
                zr = nzr; zi = nzi;
            }
        }
        __syncthreads();   // Q (and on pass 0, P) ready

        // ----- Mainloop over this pass's 16 n-rows -----
        const ulonglong2* pcBase =
            (const ulonglong2*)&sPc[pass * NP][jt * 4];

        #pragma unroll 4
        for (int m = 0; m < NP; m++) {
            float2 q0 = sQ[m][lane];
            float2 q1 = sQ[m][lane + 32];
            float2 q2 = sQ[m][lane + 64];
            float2 q3 = sQ[m][lane + 96];
            u64 qr[4] = { pack2(q0.x, q0.x), pack2(q1.x, q1.x),
                          pack2(q2.x, q2.x), pack2(q3.x, q3.x) };
            u64 qi[4] = { pack2(q0.y, q0.y), pack2(q1.y, q1.y),
                          pack2(q2.y, q2.y), pack2(q3.y, q3.y) };
            const ulonglong2* pc = pcBase + m * NJP;   // warp-uniform
            #pragma unroll
            for (int jp = 0; jp < 4; jp++) {
                ulonglong2 p = pc[jp];    // one LDS.128 broadcast: x=(px0,px1), y=(-py0,-py1)
                #pragma unroll
                for (int i = 0; i < 4; i++) {
                    acc[i][jp] = fma2(p.x, qr[i], acc[i][jp]);
                    acc[i][jp] = fma2(p.y, qi[i], acc[i][jp]);
                }
            }
        }
        __syncthreads();   // done reading sQ before next pass overwrites
    }

    // ---------- Store: coalesced across lanes ----------
    float* outh = out + (size_t)h * (size_t)L + jt * 8 * TT;
    #pragma unroll
    for (int jp = 0; jp < 4; jp++) {
        #pragma unroll
        for (int i = 0; i < 4; i++) {
            float2 v = unpack2(acc[i][jp]);
            outh[(2 * jp + 0) * TT + lane + 32 * i] = v.x;
            outh[(2 * jp + 1) * TT + lane + 32 * i] = v.y;
        }
    }
}

extern "C" void kernel_launch(void* const* d_in, const int* in_sizes, int n_in,
                              void* d_out, int out_size) {
    // inputs: [0]=L (scalar), [1]=log_dt (H), [2]=C (H,N2,2),
    //         [3]=log_A_real (H,N2), [4]=A_imag (H,N2)
    const float* log_dt     = (const float*)d_in[1];
    const float* C          = (const float*)d_in[2];
    const float* log_A_real = (const float*)d_in[3];
    const float* A_imag     = (const float*)d_in[4];
    float* out = (float*)d_out;

    int H = in_sizes[1];          // 1024
    int L = out_size / H;         // 4096  (layout assumes L/128 = 32)

    s4d_vandermonde_kernel<<<H, NTHREADS>>>(log_dt, C, log_A_real, A_imag, out, L);
}

// round 6
// speedup vs baseline: 1.5209x; 1.5209x over previous
#include <cuda_runtime.h>
#include <cuda_bf16.h>
#include <math.h>

// S4D kernel init:  out[h,l] = 2 * Re( sum_n Ccf[h,n] * exp(dtA[h,n] * l) )
// l = j*128 + i ;  out[h,j,i] = sum_n Px[n,j]*Qr[n,i] - Py[n,j]*Qi[n,i]
//
// Round-6: mainloop identical to round 4 (separate sPx/sPny LDS.64 broadcasts
// -> FFMA2 never splits). All large-argument transcendentals removed: Phase 0
// builds pw[n][k] = w^(2^k) (w = exp(dtA), small args only); Phase-1 anchors
// and Phase-2 P values are products of table entries (predicated cmuls, pure
// FFMA). Kills sincosf slow-path + MUFU serialization in the prologue.

#define N2 32
#define NP 16          // n-rows per Q pass
#define TT 128
#define TTP 129        // padded sQ row (float2 units)
#define NTHREADS 128
#define NJ 32
#define NPOW 12        // w^(2^k), k = 0..11

typedef unsigned long long u64;

__device__ __forceinline__ u64 pack2(float x, float y) {
    u64 r; asm("mov.b64 %0, {%1, %2};" : "=l"(r) : "f"(x), "f"(y)); return r;
}
__device__ __forceinline__ u64 fma2(u64 a, u64 b, u64 c) {
    u64 d; asm("fma.rn.f32x2 %0, %1, %2, %3;" : "=l"(d) : "l"(a), "l"(b), "l"(c)); return d;
}
__device__ __forceinline__ float2 unpack2(u64 v) {
    float2 f; asm("mov.b64 {%0, %1}, %2;" : "=f"(f.x), "=f"(f.y) : "l"(v)); return f;
}
__device__ __forceinline__ float2 cmul(float2 a, float2 b) {
    return make_float2(a.x * b.x - a.y * b.y, a.x * b.y + a.y * b.x);
}

__global__ __launch_bounds__(NTHREADS, 7)
void s4d_vandermonde_kernel(
    const float* __restrict__ log_dt,
    const float* __restrict__ C,          // (H, N2, 2)
    const float* __restrict__ log_A_real, // (H, N2)
    const float* __restrict__ A_imag,     // (H, N2)
    float* __restrict__ out,              // (H, L)
    int L)
{
    __shared__ float2 sQ[NP][TTP];      // 16.1 KB, padded, reused across passes
    __shared__ float  sPx[N2][NJ];      //  4 KB :  Re exp(dtA*128*j)
    __shared__ float  sPny[N2][NJ];     //  4 KB : -Im exp(dtA*128*j)
    __shared__ float2 sPow[N2][NPOW];   //  3 KB : w^(2^k)
    __shared__ float2 sCcf[N2];

    const int h    = blockIdx.x;
    const int tid  = threadIdx.x;
    const int lane = tid & 31;
    const int jt   = tid >> 5;          // warp id = j-tile (8 j each)

    // ---------- Phase 0: coefficients + power table (small-arg transcendentals only) ----------
    if (tid < N2) {
        const int n = tid;
        const int g = h * N2 + n;
        float dt  = expf(log_dt[h]);
        float ar0 = -expf(log_A_real[g]);   // Re(A)
        float ai0 = A_imag[g];              // Im(A)
        float ar  = ar0 * dt;               // Re(dtA)
        float ai  = ai0 * dt;               // Im(dtA), |ai| <= pi*31*0.1 ~ 9.7
        float er  = expf(ar), s, c;
        sincosf(ai, &s, &c);
        float2 z = make_float2(er * c, er * s);   // w = exp(dtA)
        #pragma unroll
        for (int k = 0; k < NPOW; k++) {          // pw[k] = w^(2^k)
            sPow[n][k] = z;
            z = make_float2(z.x * z.x - z.y * z.y, 2.0f * z.x * z.y);
        }
        // D = (exp(dtA) - 1) / A
        float2 w0 = sPow[n][0];
        float Er = w0.x - 1.0f, Ei = w0.y;
        float inv = 1.0f / (ar0 * ar0 + ai0 * ai0);
        float Dr = (Er * ar0 + Ei * ai0) * inv;
        float Di = (Ei * ar0 - Er * ai0) * inv;
        // Ccf = 2 * Cc * D
        float cr = C[2 * g], ci = C[2 * g + 1];
        sCcf[n] = make_float2(2.0f * (cr * Dr - ci * Di),
                              2.0f * (cr * Di + ci * Dr));
    }
    __syncthreads();

    // ---------- Phase 2: P[n][j] = w^(128*j) from power table (no MUFU) ----------
    #pragma unroll
    for (int r = 0; r < (N2 * NJ) / NTHREADS; r++) {   // 4 iters
        int idx = r * NTHREADS + tid;
        int n = idx >> 5;
        int j = idx & 31;
        float2 z = make_float2(1.0f, 0.0f);
        if (j & 1)  z = cmul(z, sPow[n][7]);
        if (j & 2)  z = cmul(z, sPow[n][8]);
        if (j & 4)  z = cmul(z, sPow[n][9]);
        if (j & 8)  z = cmul(z, sPow[n][10]);
        if (j & 16) z = cmul(z, sPow[n][11]);
        sPx[n][j]  = z.x;
        sPny[n][j] = -z.y;
    }

    // ---------- Accumulators: acc[i][jp], lo = j=8*jt+2*jp, hi = +1 ----------
    u64 acc[4][4];
    #pragma unroll
    for (int a = 0; a < 4; a++)
        #pragma unroll
        for (int b = 0; b < 4; b++) acc[a][b] = 0ULL;

    #pragma unroll
    for (int pass = 0; pass < 2; pass++) {
        // ----- Q build: anchors from power table, depth-16 recurrence -----
        {
            const int nl  = tid & 15;           // 0..15 local row (lane-fast STS)
            const int n   = pass * NP + nl;     // global n
            const int seg = tid >> 4;           // 0..7 -> i = 16*seg..
            // z = Ccf * w^(16*seg)  via bits of seg
            float2 z = sCcf[n];
            if (seg & 1) z = cmul(z, sPow[n][4]);
            if (seg & 2) z = cmul(z, sPow[n][5]);
            if (seg & 4) z = cmul(z, sPow[n][6]);
            float2 w = sPow[n][0];
            const int ibase = seg * 16;
            #pragma unroll
            for (int k = 0; k < 16; k++) {
                sQ[nl][ibase + k] = z;
                z = make_float2(z.x * w.x - z.y * w.y,
                                z.x * w.y + z.y * w.x);
            }
        }
        __syncthreads();   // Q (and on pass 0, P) ready

        // ----- Mainloop over this pass's 16 n-rows (identical to round 4) -----
        const float* pxBase  = &sPx[pass * NP][jt * 8];
        const float* pnyBase = &sPny[pass * NP][jt * 8];

        #pragma unroll 4
        for (int m = 0; m < NP; m++) {
            float2 q0 = sQ[m][lane];
            float2 q1 = sQ[m][lane + 32];
            float2 q2 = sQ[m][lane + 64];
            float2 q3 = sQ[m][lane + 96];
            u64 qr[4] = { pack2(q0.x, q0.x), pack2(q1.x, q1.x),
                          pack2(q2.x, q2.x), pack2(q3.x, q3.x) };
            u64 qi[4] = { pack2(q0.y, q0.y), pack2(q1.y, q1.y),
                          pack2(q2.y, q2.y), pack2(q3.y, q3.y) };
            const u64* px  = (const u64*)(pxBase  + m * NJ);  // warp-uniform
            const u64* pny = (const u64*)(pnyBase + m * NJ);  // broadcasts
            #pragma unroll
            for (int jp = 0; jp < 4; jp++) {
                u64 pxv  = px[jp];
                u64 pnyv = pny[jp];
                #pragma unroll
                for (int i = 0; i < 4; i++) {
                    acc[i][jp] = fma2(pxv,  qr[i], acc[i][jp]);
                    acc[i][jp] = fma2(pnyv, qi[i], acc[i][jp]);
                }
            }
        }
        __syncthreads();   // done reading sQ before next pass overwrites
    }

    // ---------- Store: coalesced across lanes ----------
    float* outh = out + (size_t)h * (size_t)L + jt * 8 * TT;
    #pragma unroll
    for (int jp = 0; jp < 4; jp++) {
        #pragma unroll
        for (int i = 0; i < 4; i++) {
            float2 v = unpack2(acc[i][jp]);
            outh[(2 * jp + 0) * TT + lane + 32 * i] = v.x;
            outh[(2 * jp + 1) * TT + lane + 32 * i] = v.y;
        }
    }
}

extern "C" void kernel_launch(void* const* d_in, const int* in_sizes, int n_in,
                              void* d_out, int out_size) {
    // inputs: [0]=L (scalar), [1]=log_dt (H), [2]=C (H,N2,2),
    //         [3]=log_A_real (H,N2), [4]=A_imag (H,N2)
    const float* log_dt     = (const float*)d_in[1];
    const float* C          = (const float*)d_in[2];
    const float* log_A_real = (const float*)d_in[3];
    const float* A_imag     = (const float*)d_in[4];
    float* out = (float*)d_out;

    int H = in_sizes[1];          // 1024
    int L = out_size / H;         // 4096  (layout assumes L/128 = 32)

    s4d_vandermonde_kernel<<<H, NTHREADS>>>(log_dt, C, log_A_real, A_imag, out, L);
}

// round 7
// speedup vs baseline: 1.7287x; 1.1366x over previous
#include <cuda_runtime.h>
#include <cuda_bf16.h>
#include <math.h>

// S4D kernel init:  out[h,l] = 2 * Re( sum_n Ccf[h,n] * exp(dtA[h,n] * l) )
// l = j*128 + i ;  out[h,j,i] = sum_n Px[n,j]*Qr[n,i] - Py[n,j]*Qi[n,i]
//
// Round-7:
//  * P fused to float4 (px0,px1,-py0,-py1): ONE LDS.128 broadcast per j-pair,
//    unpacked via explicit mov.b64 scalar packs (never feeds a 128-bit load
//    pair straight into fma.rn.f32x2 -> no FFMA splitting).
//    Crossbar: 16 -> 12 wf per warp per n; fma pipe becomes sole bottleneck.
//  * Explicit double-buffered pipeline over n (Q+P prefetch one iteration
//    ahead), launch_bounds(128,5) for the register budget ptxas needs to
//    keep loads of n+1 in flight under the FMAs of n.

#define N2 32
#define NP 16          // n-rows per Q pass
#define TT 128
#define TTP 129        // padded sQ row (float2 units)
#define NTHREADS 128
#define NJ 32
#define NJP 16         // j-pairs
#define NPOW 12        // w^(2^k), k = 0..11

typedef unsigned long long u64;

__device__ __forceinline__ u64 pack2(float x, float y) {
    u64 r; asm("mov.b64 %0, {%1, %2};" : "=l"(r) : "f"(x), "f"(y)); return r;
}
__device__ __forceinline__ u64 fma2(u64 a, u64 b, u64 c) {
    u64 d; asm("fma.rn.f32x2 %0, %1, %2, %3;" : "=l"(d) : "l"(a), "l"(b), "l"(c)); return d;
}
__device__ __forceinline__ float2 unpack2(u64 v) {
    float2 f; asm("mov.b64 {%0, %1}, %2;" : "=f"(f.x), "=f"(f.y) : "l"(v)); return f;
}
__device__ __forceinline__ float2 cmul(float2 a, float2 b) {
    return make_float2(a.x * b.x - a.y * b.y, a.x * b.y + a.y * b.x);
}

__global__ __launch_bounds__(NTHREADS, 5)
void s4d_vandermonde_kernel(
    const float* __restrict__ log_dt,
    const float* __restrict__ C,          // (H, N2, 2)
    const float* __restrict__ log_A_real, // (H, N2)
    const float* __restrict__ A_imag,     // (H, N2)
    float* __restrict__ out,              // (H, L)
    int L)
{
    __shared__ float2 sQ[NP][TTP];      // 16.1 KB, padded, reused across passes
    __shared__ float4 sPc[N2][NJP];     //  8 KB : (px0, px1, -py0, -py1)
    __shared__ float2 sPow[N2][NPOW];   //  3 KB : w^(2^k)
    __shared__ float2 sCcf[N2];

    const int h    = blockIdx.x;
    const int tid  = threadIdx.x;
    const int lane = tid & 31;
    const int jt   = tid >> 5;          // warp id = j-tile (8 j = 4 pairs)

    // ---------- Phase 0: coefficients + power table ----------
    if (tid < N2) {
        const int n = tid;
        const int g = h * N2 + n;
        float dt  = expf(log_dt[h]);
        float ar0 = -expf(log_A_real[g]);   // Re(A)
        float ai0 = A_imag[g];              // Im(A)
        float ar  = ar0 * dt;               // Re(dtA)
        float ai  = ai0 * dt;               // Im(dtA)
        float er  = expf(ar), s, c;
        sincosf(ai, &s, &c);
        float2 z = make_float2(er * c, er * s);   // w = exp(dtA)
        #pragma unroll
        for (int k = 0; k < NPOW; k++) {          // pw[k] = w^(2^k)
            sPow[n][k] = z;
            z = make_float2(z.x * z.x - z.y * z.y, 2.0f * z.x * z.y);
        }
        // D = (exp(dtA) - 1) / A
        float2 w0 = sPow[n][0];
        float Er = w0.x - 1.0f, Ei = w0.y;
        float inv = 1.0f / (ar0 * ar0 + ai0 * ai0);
        float Dr = (Er * ar0 + Ei * ai0) * inv;
        float Di = (Ei * ar0 - Er * ai0) * inv;
        // Ccf = 2 * Cc * D
        float cr = C[2 * g], ci = C[2 * g + 1];
        sCcf[n] = make_float2(2.0f * (cr * Dr - ci * Di),
                              2.0f * (cr * Di + ci * Dr));
    }
    __syncthreads();

    // ---------- Phase 2: fused P from power table ----------
    // sPc[n][jp] = ( Re w^(256jp), Re w^(256jp+128), -Im w^(256jp), -Im w^(256jp+128) )
    #pragma unroll
    for (int r = 0; r < (N2 * NJP) / NTHREADS; r++) {   // 4 iters
        int idx = r * NTHREADS + tid;
        int n   = idx >> 4;         // 0..31
        int jp  = idx & 15;         // j-pair
        int j0  = 2 * jp;
        float2 z0 = make_float2(1.0f, 0.0f);
        if (j0 & 2)  z0 = cmul(z0, sPow[n][8]);
        if (j0 & 4)  z0 = cmul(z0, sPow[n][9]);
        if (j0 & 8)  z0 = cmul(z0, sPow[n][10]);
        if (j0 & 16) z0 = cmul(z0, sPow[n][11]);
        float2 z1 = cmul(z0, sPow[n][7]);       // j0+1
        sPc[n][jp] = make_float4(z0.x, z1.x, -z0.y, -z1.y);
    }

    // ---------- Accumulators: acc[i][jp], lo = j=8*jt+2*jp, hi = +1 ----------
    u64 acc[4][4];
    #pragma unroll
    for (int a = 0; a < 4; a++)
        #pragma unroll
        for (int b = 0; b < 4; b++) acc[a][b] = 0ULL;

    #pragma unroll
    for (int pass = 0; pass < 2; pass++) {
        // ----- Q build: anchors from table, depth-16 recurrence, lane-fast STS -----
        {
            const int nl  = tid & 15;           // 0..15 local row
            const int n   = pass * NP + nl;     // global n
            const int seg = tid >> 4;           // 0..7 -> i = 16*seg..
            float2 z = sCcf[n];
            if (seg & 1) z = cmul(z, sPow[n][4]);
            if (seg & 2) z = cmul(z, sPow[n][5]);
            if (seg & 4) z = cmul(z, sPow[n][6]);
            float2 w = sPow[n][0];
            const int ibase = seg * 16;
            #pragma unroll
            for (int k = 0; k < 16; k++) {
                sQ[nl][ibase + k] = z;
                z = make_float2(z.x * w.x - z.y * w.y,
                                z.x * w.y + z.y * w.x);
            }
        }
        __syncthreads();   // Q (and on pass 0, P) ready

        // ----- Mainloop: double-buffered over 16 n-rows -----
        const float4* pc = &sPc[pass * NP][0] + jt * 4;  // row stride NJP float4

        float2 qb[2][4];
        float4 pb[2][4];
        // prefetch m = 0
        qb[0][0] = sQ[0][lane];
        qb[0][1] = sQ[0][lane + 32];
        qb[0][2] = sQ[0][lane + 64];
        qb[0][3] = sQ[0][lane + 96];
        #pragma unroll
        for (int k = 0; k < 4; k++) pb[0][k] = pc[k];

        #pragma unroll
        for (int m = 0; m < NP; m++) {
            const int cur = m & 1, nxt = cur ^ 1;
            if (m + 1 < NP) {   // prefetch next n
                qb[nxt][0] = sQ[m + 1][lane];
                qb[nxt][1] = sQ[m + 1][lane + 32];
                qb[nxt][2] = sQ[m + 1][lane + 64];
                qb[nxt][3] = sQ[m + 1][lane + 96];
                #pragma unroll
                for (int k = 0; k < 4; k++) pb[nxt][k] = pc[(m + 1) * NJP + k];
            }
            // unpack P (scalar packs -> never splits fma2)
            u64 pxv[4], pnyv[4];
            #pragma unroll
            for (int jp = 0; jp < 4; jp++) {
                pxv[jp]  = pack2(pb[cur][jp].x, pb[cur][jp].y);
                pnyv[jp] = pack2(pb[cur][jp].z, pb[cur][jp].w);
            }
            #pragma unroll
            for (int i = 0; i < 4; i++) {
                u64 qr = pack2(qb[cur][i].x, qb[cur][i].x);
                u64 qi = pack2(qb[cur][i].y, qb[cur][i].y);
                #pragma unroll
                for (int jp = 0; jp < 4; jp++) {
                    acc[i][jp] = fma2(pxv[jp],  qr, acc[i][jp]);
                    acc[i][jp] = fma2(pnyv[jp], qi, acc[i][jp]);
                }
            }
        }
        __syncthreads();   // done reading sQ before next pass overwrites
    }

    // ---------- Store: coalesced across lanes ----------
    float* outh = out + (size_t)h * (size_t)L + jt * 8 * TT;
    #pragma unroll
    for (int jp = 0; jp < 4; jp++) {
        #pragma unroll
        for (int i = 0; i < 4; i++) {
            float2 v = unpack2(acc[i][jp]);
            outh[(2 * jp + 0) * TT + lane + 32 * i] = v.x;
            outh[(2 * jp + 1) * TT + lane + 32 * i] = v.y;
        }
    }
}

extern "C" void kernel_launch(void* const* d_in, const int* in_sizes, int n_in,
                              void* d_out, int out_size) {
    // inputs: [0]=L (scalar), [1]=log_dt (H), [2]=C (H,N2,2),
    //         [3]=log_A_real (H,N2), [4]=A_imag (H,N2)
    const float* log_dt     = (const float*)d_in[1];
    const float* C          = (const float*)d_in[2];
    const float* log_A_real = (const float*)d_in[3];
    const float* A_imag     = (const float*)d_in[4];
    float* out = (float*)d_out;

    int H = in_sizes[1];          // 1024
    int L = out_size / H;         // 4096  (layout assumes L/128 = 32)

    s4d_vandermonde_kernel<<<H, NTHREADS>>>(log_dt, C, log_A_real, A_imag, out, L);
}